// round 1
// baseline (speedup 1.0000x reference)
#include <cuda_runtime.h>

// FIRApply: y[t] = sum_{k=0}^{15} b[k] * x[t-k], zero initial state.
// x: [64, 480000] f32, b: [16] f32, y: [64, 480000] f32.

#define BATCH  64
#define T_LEN  480000
#define NTAPS  16
#define OPT    8          // outputs per thread
#define TPB    256        // threads per block
#define OPB    (OPT*TPB)  // outputs per block = 2048

__global__ __launch_bounds__(TPB)
void fir_kernel(const float* __restrict__ x,
                const float* __restrict__ b,
                float* __restrict__ y)
{
    const int row = blockIdx.y;
    const int t0  = blockIdx.x * OPB + threadIdx.x * OPT;  // first output idx
    if (t0 >= T_LEN) return;

    const float* __restrict__ xr = x + (long long)row * T_LEN;
    float*       __restrict__ yr = y + (long long)row * T_LEN;

    // taps -> registers (uniform address: broadcast, L1-resident)
    float bb[NTAPS];
#pragma unroll
    for (int k = 0; k < NTAPS; k++) bb[k] = __ldg(b + k);

    // window w[q] = x[t0 - 16 + q], q = 0..23  (covers x[t0-15 .. t0+7]; w[0] unused)
    float w[24];
    const int g0 = t0 - 16;           // multiple of 8 -> 32B aligned
    if (g0 >= 0) {
        // T_LEN % 8 == 0 and t0 < T_LEN  =>  t0+7 < T_LEN always: full fast path
#pragma unroll
        for (int c = 0; c < 6; c++) {
            float4 v = *reinterpret_cast<const float4*>(xr + g0 + 4 * c);
            w[4*c+0] = v.x; w[4*c+1] = v.y; w[4*c+2] = v.z; w[4*c+3] = v.w;
        }
    } else {
        // left edge of the row (t0 < 16): zero-pad history
#pragma unroll
        for (int q = 0; q < 24; q++) {
            const int g = g0 + q;
            w[q] = (g >= 0) ? xr[g] : 0.0f;
        }
    }

    // y[t0+o] = sum_k bb[k] * w[o + 16 - k]
    float acc[OPT];
#pragma unroll
    for (int o = 0; o < OPT; o++) {
        float s = 0.0f;
#pragma unroll
        for (int k = 0; k < NTAPS; k++)
            s = fmaf(bb[k], w[o + 16 - k], s);
        acc[o] = s;
    }

    // two aligned float4 stores
    float4 s0 = make_float4(acc[0], acc[1], acc[2], acc[3]);
    float4 s1 = make_float4(acc[4], acc[5], acc[6], acc[7]);
    *reinterpret_cast<float4*>(yr + t0)     = s0;
    *reinterpret_cast<float4*>(yr + t0 + 4) = s1;
}

extern "C" void kernel_launch(void* const* d_in, const int* in_sizes, int n_in,
                              void* d_out, int out_size)
{
    const float* x = (const float*)d_in[0];
    const float* b = (const float*)d_in[1];
    float* y = (float*)d_out;

    dim3 grid((T_LEN + OPB - 1) / OPB, BATCH);  // (235, 64)
    fir_kernel<<<grid, TPB>>>(x, b, y);
}